// round 14
// baseline (speedup 1.0000x reference)
#include <cuda_runtime.h>
#include <cuda_fp16.h>
#include <cstdint>

#define NN 100000
#define NR 8
#define NE 150000
#define DD 128
#define MT 128
#define NTILES ((NN + MT - 1) / MT)
#define CHUNK 1024
#define NCHUNK ((NN + CHUNK - 1) / CHUNK)   // 98

// Scratch (device globals: allocation-free per harness rules)
__device__ int g_cnt[2 * NR * NN];   // [0]: in-degree, [NR*NN]: fill cursors
__device__ int g_rowptr[NR * NN];    // CSR chunk-local exclusive offsets
__device__ int g_csum[NR * NCHUNK];  // per-chunk sums
__device__ int g_coff[NR * NCHUNK];  // per-chunk exclusive offsets
__device__ int g_esrc[NR * NE];      // CSR src lists
// W (fp16) in mma-fragment order: [rel(9)][kk(8)][pair(8)][lane(32)] x uint4
__device__ __align__(16) uint4 g_wf[9 * 8 * 8 * 32];      // 288 KB

// ---------------------------------------------------------------- index dtype
__device__ __forceinline__ bool idx_is64(const int* p) {
    return (p[1] | p[3] | p[5] | p[7]) == 0;
}
__device__ __forceinline__ int idx_at(const void* p, size_t i, bool is64) {
    return is64 ? (int)((const long long*)p)[i] : ((const int*)p)[i];
}

__device__ __forceinline__ uint32_t pack_h2(float a, float b) {
    __half2 h = __floats2half2_rn(a, b);
    return *(uint32_t*)&h;
}

// ---------------------------------------------------------------- setup kernels
__global__ void count_deg_kernel(const void* __restrict__ dst) {
    bool is64 = idx_is64((const int*)dst);
    int e = blockIdx.x * blockDim.x + threadIdx.x;
    int r = blockIdx.y;
    if (e < NE) {
        int d = idx_at(dst, (size_t)r * NE + e, is64);
        atomicAdd(&g_cnt[r * NN + d], 1);
    }
}

// W prep (fp16) into fragment order, element gi. rel 8 = self-loop weight.
__device__ void prep_w_elem(int gi, const float* w, const float* wsl) {
    int lane = gi & 31, p = (gi >> 5) & 7, kk = (gi >> 8) & 7, rel = gi >> 11;
    int g = lane >> 2, tk = lane & 3;
    const float* B = (rel < 8) ? w + (size_t)rel * DD * DD : wsl;
    int k0 = kk * 16 + tk * 2;
    int nA = p * 16 + g, nB = nA + 8;
    g_wf[gi] = make_uint4(
        pack_h2(B[(k0 + 0) * DD + nA], B[(k0 + 1) * DD + nA]),
        pack_h2(B[(k0 + 8) * DD + nA], B[(k0 + 9) * DD + nA]),
        pack_h2(B[(k0 + 0) * DD + nB], B[(k0 + 1) * DD + nB]),
        pack_h2(B[(k0 + 8) * DD + nB], B[(k0 + 9) * DD + nB]));
}

// Phase A: per-chunk exclusive scan + chunk totals; spare blocks do W prep.
// grid (NCHUNK, NR), 1024 thr.
__global__ void scan_a_kernel(const float* __restrict__ w,
                              const float* __restrict__ wsl) {
    int r = blockIdx.y, c = blockIdx.x;
    int t = threadIdx.x, lane = t & 31, wid = t >> 5;
    // fused W prep on the first 18 linear blocks
    int bid = blockIdx.y * gridDim.x + blockIdx.x;
    int gi = bid * 1024 + t;
    if (gi < 9 * 8 * 8 * 32) prep_w_elem(gi, w, wsl);

    __shared__ int wsum[32];
    int i = c * CHUNK + t;
    int v = (i < NN) ? g_cnt[r * NN + i] : 0;
    int s = v;
#pragma unroll
    for (int off = 1; off < 32; off <<= 1) {
        int n = __shfl_up_sync(0xFFFFFFFFu, s, off);
        if (lane >= off) s += n;
    }
    if (lane == 31) wsum[wid] = s;
    __syncthreads();
    if (wid == 0) {
        int ws = wsum[lane];
#pragma unroll
        for (int off = 1; off < 32; off <<= 1) {
            int n = __shfl_up_sync(0xFFFFFFFFu, ws, off);
            if (lane >= off) ws += n;
        }
        wsum[lane] = ws;
    }
    __syncthreads();
    int incl = s + (wid > 0 ? wsum[wid - 1] : 0);
    if (i < NN) g_rowptr[r * NN + i] = incl - v;      // chunk-local exclusive
    if (t == 1023) g_csum[r * NCHUNK + c] = incl;
}

// Phase B: scan chunk totals. 1 block; warp r handles relation r.
__global__ void scan_b_kernel() {
    int lane = threadIdx.x & 31, r = threadIdx.x >> 5;
    if (r >= NR) return;
    int carry = 0;
    for (int base = 0; base < NCHUNK; base += 32) {
        int idx = base + lane;
        int v = (idx < NCHUNK) ? g_csum[r * NCHUNK + idx] : 0;
        int s = v;
#pragma unroll
        for (int off = 1; off < 32; off <<= 1) {
            int n = __shfl_up_sync(0xFFFFFFFFu, s, off);
            if (lane >= off) s += n;
        }
        if (idx < NCHUNK) g_coff[r * NCHUNK + idx] = carry + s - v;
        carry += __shfl_sync(0xFFFFFFFFu, s, 31);
    }
}

__global__ void fill_kernel(const void* __restrict__ src,
                            const void* __restrict__ dst) {
    bool is64 = idx_is64((const int*)dst);
    int e = blockIdx.x * blockDim.x + threadIdx.x;
    int r = blockIdx.y;
    if (e < NE) {
        int s = idx_at(src, (size_t)r * NE + e, is64);
        int d = idx_at(dst, (size_t)r * NE + e, is64);
        int pos = atomicAdd(&g_cnt[NR * NN + r * NN + d], 1);
        int base = g_rowptr[r * NN + d] + g_coff[r * NCHUNK + (d >> 10)];
        g_esrc[(size_t)r * NE + base + pos] = s;
    }
}

// ---------------------------------------------------------------- mma helpers
__device__ __forceinline__ uint32_t smem_u32(const void* p) {
    uint32_t a;
    asm("{ .reg .u64 t; cvta.to.shared.u64 t, %1; cvt.u32.u64 %0, t; }"
        : "=r"(a) : "l"(p));
    return a;
}
__device__ __forceinline__ void ldsm4(uint32_t* a, uint32_t addr) {
    asm volatile("ldmatrix.sync.aligned.m8n8.x4.shared.b16 {%0,%1,%2,%3}, [%4];"
                 : "=r"(a[0]), "=r"(a[1]), "=r"(a[2]), "=r"(a[3]) : "r"(addr));
}
__device__ __forceinline__ void mma16816(float* c, const uint32_t* a,
                                         uint32_t b0, uint32_t b1) {
    asm volatile(
        "mma.sync.aligned.m16n8k16.row.col.f32.f16.f16.f32 "
        "{%0,%1,%2,%3}, {%4,%5,%6,%7}, {%8,%9}, {%0,%1,%2,%3};"
        : "+f"(c[0]), "+f"(c[1]), "+f"(c[2]), "+f"(c[3])
        : "r"(a[0]), "r"(a[1]), "r"(a[2]), "r"(a[3]), "r"(b0), "r"(b1));
}

// ---------------------------------------------------------------- fused kernel
// One 128-row tile per block; 3 blocks/SM (reg cap 85). Per relation:
// MMA(current buffer) first, then next relation's gather into the other
// buffer — gather latency hides behind tensor work of 24 warps/SM.
#define ARS 272                       // A smem row stride, bytes (128 fp16 + pad)
#define A_PLANE (128 * ARS)           // 34816 B per buffer
#define GEMM_SMEM (2 * A_PLANE)       // 69632 B

__global__ __launch_bounds__(256, 3)
void fused_gemm_kernel(const float* __restrict__ x,
                       const float* __restrict__ bias,
                       float* __restrict__ C) {
    extern __shared__ char sm[];
    int tid = threadIdx.x, lane = tid & 31, w = tid >> 5;
    int wm = w & 1, wn = w >> 1;
    int row0 = blockIdx.x * MT;

    float acc[4][4][4];
#pragma unroll
    for (int i = 0; i < 4; i++)
#pragma unroll
        for (int j = 0; j < 4; j++)
#pragma unroll
            for (int q = 0; q < 4; q++) acc[i][j][q] = 0.f;

    uint32_t sb = smem_u32(sm);
    uint32_t aBase = sb + (wm * 64 + (lane & 15)) * ARS + (lane >> 4) * 16;

    // gather+convert one relation's A tile: 8 threads/row, 4 passes
    auto gatherA = [&](int rel, int buf) {          // rel<0 -> A = x
        char* bp = sm + buf * A_PLANE;
#pragma unroll
        for (int pass = 0; pass < 4; pass++) {
            int row = pass * 32 + (tid >> 3);
            int oct = tid & 7;                       // 16-float chunk of the row
            int grow = row0 + row;
            char* hiB = bp + row * ARS + oct * 32;
            float4 a4[4];
#pragma unroll
            for (int j = 0; j < 4; j++) a4[j] = make_float4(0.f, 0.f, 0.f, 0.f);
            if (grow < NN) {
                if (rel < 0) {
                    const float4* Ar = (const float4*)x + (size_t)grow * 32 + oct * 4;
#pragma unroll
                    for (int j = 0; j < 4; j++) a4[j] = Ar[j];
                } else {
                    int dg = g_cnt[rel * NN + grow];
                    int rp = g_rowptr[rel * NN + grow] +
                             g_coff[rel * NCHUNK + (grow >> 10)];
                    const int* ep = g_esrc + (size_t)rel * NE + rp;
                    for (int e = 0; e < dg; e++) {
                        int s = ep[e];
                        const float4* Xr = (const float4*)x + (size_t)s * 32 + oct * 4;
#pragma unroll
                        for (int j = 0; j < 4; j++) {
                            float4 v = Xr[j];
                            a4[j].x += v.x; a4[j].y += v.y;
                            a4[j].z += v.z; a4[j].w += v.w;
                        }
                    }
                    float sc = 1.f / (float)(dg > 1 ? dg : 1);
#pragma unroll
                    for (int j = 0; j < 4; j++) {
                        a4[j].x *= sc; a4[j].y *= sc;
                        a4[j].z *= sc; a4[j].w *= sc;
                    }
                }
            }
#pragma unroll
            for (int j = 0; j < 4; j++) {
                *(uint2*)(hiB + j * 8) =
                    make_uint2(pack_h2(a4[j].x, a4[j].y),
                               pack_h2(a4[j].z, a4[j].w));
            }
        }
    };

    gatherA(-1, 0);                                  // rs=0: self-loop, buf 0
    __syncthreads();

    for (int rs = 0; rs < 9; rs++) {
        // ---- MMA on current buffer FIRST (tensor pipe goes busy immediately)
        int wsel = (rs == 0) ? 8 : rs - 1;
        uint32_t ab = aBase + (rs & 1) * A_PLANE;
        const uint4* WF = g_wf + ((size_t)wsel * 64 + wn * 2) * 32 + lane;
#pragma unroll
        for (int kk = 0; kk < 8; kk++) {
            uint4 f0 = WF[kk * 8 * 32], f1 = WF[kk * 8 * 32 + 32];
#pragma unroll
            for (int i = 0; i < 4; i++) {
                uint32_t a[4];
                ldsm4(a, ab + i * 16 * ARS + kk * 32);
                mma16816(acc[i][0], a, f0.x, f0.y);
                mma16816(acc[i][1], a, f0.z, f0.w);
                mma16816(acc[i][2], a, f1.x, f1.y);
                mma16816(acc[i][3], a, f1.z, f1.w);
            }
        }
        // ---- then prefetch next relation into the other buffer
        if (rs < 8) gatherA(rs, (rs + 1) & 1);
        __syncthreads();
    }

    // ---- single epilogue: + bias, relu, store
    int g = lane >> 2, tk = lane & 3;
#pragma unroll
    for (int i = 0; i < 4; i++) {
        int r1 = row0 + wm * 64 + i * 16 + g;
#pragma unroll
        for (int jl = 0; jl < 4; jl++) {
            int c = wn * 32 + jl * 8 + tk * 2;
            float b0 = bias[c], b1 = bias[c + 1];
#pragma unroll
            for (int h = 0; h < 2; h++) {
                int row = r1 + h * 8;
                if (row < NN) {
                    float2 v = make_float2(
                        fmaxf(acc[i][jl][h * 2] + b0, 0.f),
                        fmaxf(acc[i][jl][h * 2 + 1] + b1, 0.f));
                    *(float2*)(C + (size_t)row * DD + c) = v;
                }
            }
        }
    }
}

// ---------------------------------------------------------------- launch
extern "C" void kernel_launch(void* const* d_in, const int* in_sizes, int n_in,
                              void* d_out, int out_size) {
    const float* x    = (const float*)d_in[0];
    const float* w    = (const float*)d_in[1];
    const float* wsl  = (const float*)d_in[2];
    const float* bias = (const float*)d_in[3];
    const void* src   = d_in[4];
    const void* dst   = d_in[5];
    float* out = (float*)d_out;

    cudaFuncSetAttribute(fused_gemm_kernel,
                         cudaFuncAttributeMaxDynamicSharedMemorySize, GEMM_SMEM);

    // launch 0: zero deg+fill in one memset
    void* p_cnt = nullptr;
    cudaGetSymbolAddress(&p_cnt, g_cnt);
    cudaMemsetAsync(p_cnt, 0, sizeof(int) * 2 * NR * NN);

    // launches 1-4: CSR build (+W prep fused into scan_a)
    dim3 cg((NE + 255) / 256, NR);
    count_deg_kernel<<<cg, 256>>>(dst);
    dim3 sg(NCHUNK, NR);
    scan_a_kernel<<<sg, 1024>>>(w, wsl);
    scan_b_kernel<<<1, 256>>>();
    fill_kernel<<<cg, 256>>>(src, dst);

    // launch 5 (ncu -s 5 hits this): gather + 9 fp16 GEMM passes + epilogue
    fused_gemm_kernel<<<NTILES, 256, GEMM_SMEM>>>(x, bias, out);
}

// round 16
// speedup vs baseline: 1.3119x; 1.3119x over previous
#include <cuda_runtime.h>
#include <cuda_fp16.h>
#include <cstdint>

#define NN 100000
#define NR 8
#define NE 150000
#define DD 128
#define MT 128
#define NTILES ((NN + MT - 1) / MT)
#define CHUNK 1024
#define NCHUNK ((NN + CHUNK - 1) / CHUNK)   // 98

// Scratch (device globals: allocation-free per harness rules)
__device__ int g_cnt[2 * NR * NN];   // [0]: in-degree, [NR*NN]: fill cursors
__device__ int g_rowptr[NR * NN];    // CSR chunk-local exclusive offsets
__device__ int g_csum[NR * NCHUNK];  // per-chunk sums
__device__ int g_coff[NR * NCHUNK];  // per-chunk exclusive offsets
__device__ int g_esrc[NR * NE];      // CSR src lists
// W (fp16) in mma-fragment order: [rel(9)][kk(8)][pair(8)][lane(32)] x uint4
__device__ __align__(16) uint4 g_wf[9 * 8 * 8 * 32];      // 288 KB

// ---------------------------------------------------------------- index dtype
__device__ __forceinline__ bool idx_is64(const int* p) {
    return (p[1] | p[3] | p[5] | p[7]) == 0;
}
__device__ __forceinline__ int idx_at(const void* p, size_t i, bool is64) {
    return is64 ? (int)((const long long*)p)[i] : ((const int*)p)[i];
}

__device__ __forceinline__ uint32_t pack_h2(float a, float b) {
    __half2 h = __floats2half2_rn(a, b);
    return *(uint32_t*)&h;
}

// ---------------------------------------------------------------- setup kernels
__global__ void count_deg_kernel(const void* __restrict__ dst) {
    bool is64 = idx_is64((const int*)dst);
    int e = blockIdx.x * blockDim.x + threadIdx.x;
    int r = blockIdx.y;
    if (e < NE) {
        int d = idx_at(dst, (size_t)r * NE + e, is64);
        atomicAdd(&g_cnt[r * NN + d], 1);
    }
}

// W prep (fp16) into fragment order, element gi. rel 8 = self-loop weight.
__device__ void prep_w_elem(int gi, const float* w, const float* wsl) {
    int lane = gi & 31, p = (gi >> 5) & 7, kk = (gi >> 8) & 7, rel = gi >> 11;
    int g = lane >> 2, tk = lane & 3;
    const float* B = (rel < 8) ? w + (size_t)rel * DD * DD : wsl;
    int k0 = kk * 16 + tk * 2;
    int nA = p * 16 + g, nB = nA + 8;
    g_wf[gi] = make_uint4(
        pack_h2(B[(k0 + 0) * DD + nA], B[(k0 + 1) * DD + nA]),
        pack_h2(B[(k0 + 8) * DD + nA], B[(k0 + 9) * DD + nA]),
        pack_h2(B[(k0 + 0) * DD + nB], B[(k0 + 1) * DD + nB]),
        pack_h2(B[(k0 + 8) * DD + nB], B[(k0 + 9) * DD + nB]));
}

// Phase A: per-chunk exclusive scan + chunk totals; spare blocks do W prep.
// grid (NCHUNK, NR), 1024 thr.
__global__ void scan_a_kernel(const float* __restrict__ w,
                              const float* __restrict__ wsl) {
    int r = blockIdx.y, c = blockIdx.x;
    int t = threadIdx.x, lane = t & 31, wid = t >> 5;
    // fused W prep on the first 18 linear blocks
    int bid = blockIdx.y * gridDim.x + blockIdx.x;
    int gi = bid * 1024 + t;
    if (gi < 9 * 8 * 8 * 32) prep_w_elem(gi, w, wsl);

    __shared__ int wsum[32];
    int i = c * CHUNK + t;
    int v = (i < NN) ? g_cnt[r * NN + i] : 0;
    int s = v;
#pragma unroll
    for (int off = 1; off < 32; off <<= 1) {
        int n = __shfl_up_sync(0xFFFFFFFFu, s, off);
        if (lane >= off) s += n;
    }
    if (lane == 31) wsum[wid] = s;
    __syncthreads();
    if (wid == 0) {
        int ws = wsum[lane];
#pragma unroll
        for (int off = 1; off < 32; off <<= 1) {
            int n = __shfl_up_sync(0xFFFFFFFFu, ws, off);
            if (lane >= off) ws += n;
        }
        wsum[lane] = ws;
    }
    __syncthreads();
    int incl = s + (wid > 0 ? wsum[wid - 1] : 0);
    if (i < NN) g_rowptr[r * NN + i] = incl - v;      // chunk-local exclusive
    if (t == 1023) g_csum[r * NCHUNK + c] = incl;
}

// Phase B: scan chunk totals. 1 block; warp r handles relation r.
__global__ void scan_b_kernel() {
    int lane = threadIdx.x & 31, r = threadIdx.x >> 5;
    if (r >= NR) return;
    int carry = 0;
    for (int base = 0; base < NCHUNK; base += 32) {
        int idx = base + lane;
        int v = (idx < NCHUNK) ? g_csum[r * NCHUNK + idx] : 0;
        int s = v;
#pragma unroll
        for (int off = 1; off < 32; off <<= 1) {
            int n = __shfl_up_sync(0xFFFFFFFFu, s, off);
            if (lane >= off) s += n;
        }
        if (idx < NCHUNK) g_coff[r * NCHUNK + idx] = carry + s - v;
        carry += __shfl_sync(0xFFFFFFFFu, s, 31);
    }
}

__global__ void fill_kernel(const void* __restrict__ src,
                            const void* __restrict__ dst) {
    bool is64 = idx_is64((const int*)dst);
    int e = blockIdx.x * blockDim.x + threadIdx.x;
    int r = blockIdx.y;
    if (e < NE) {
        int s = idx_at(src, (size_t)r * NE + e, is64);
        int d = idx_at(dst, (size_t)r * NE + e, is64);
        int pos = atomicAdd(&g_cnt[NR * NN + r * NN + d], 1);
        int base = g_rowptr[r * NN + d] + g_coff[r * NCHUNK + (d >> 10)];
        g_esrc[(size_t)r * NE + base + pos] = s;
    }
}

// ---------------------------------------------------------------- mma helpers
__device__ __forceinline__ uint32_t smem_u32(const void* p) {
    uint32_t a;
    asm("{ .reg .u64 t; cvta.to.shared.u64 t, %1; cvt.u32.u64 %0, t; }"
        : "=r"(a) : "l"(p));
    return a;
}
__device__ __forceinline__ void ldsm4(uint32_t* a, uint32_t addr) {
    asm volatile("ldmatrix.sync.aligned.m8n8.x4.shared.b16 {%0,%1,%2,%3}, [%4];"
                 : "=r"(a[0]), "=r"(a[1]), "=r"(a[2]), "=r"(a[3]) : "r"(addr));
}
__device__ __forceinline__ void mma16816(float* c, const uint32_t* a,
                                         uint32_t b0, uint32_t b1) {
    asm volatile(
        "mma.sync.aligned.m16n8k16.row.col.f32.f16.f16.f32 "
        "{%0,%1,%2,%3}, {%4,%5,%6,%7}, {%8,%9}, {%0,%1,%2,%3};"
        : "+f"(c[0]), "+f"(c[1]), "+f"(c[2]), "+f"(c[3])
        : "r"(a[0]), "r"(a[1]), "r"(a[2]), "r"(a[3]), "r"(b0), "r"(b1));
}

// ---------------------------------------------------------------- fused kernel
// Round-11 proven shape: one 128-row tile per block; 2 blocks/SM; per
// relation MMA(current buffer) first (batched ldsm4 x4 for ILP), then the
// next relation's gather (4 threads/row, 2 passes) into the other buffer.
#define ARS 272                       // A smem row stride, bytes (128 fp16 + pad)
#define A_PLANE (128 * ARS)           // 34816 B per buffer
#define GEMM_SMEM (2 * A_PLANE)       // 69632 B

__global__ __launch_bounds__(256, 2)
void fused_gemm_kernel(const float* __restrict__ x,
                       const float* __restrict__ bias,
                       float* __restrict__ C) {
    extern __shared__ char sm[];
    int tid = threadIdx.x, lane = tid & 31, w = tid >> 5;
    int wm = w & 1, wn = w >> 1;
    int row0 = blockIdx.x * MT;

    float acc[4][4][4];
#pragma unroll
    for (int i = 0; i < 4; i++)
#pragma unroll
        for (int j = 0; j < 4; j++)
#pragma unroll
            for (int q = 0; q < 4; q++) acc[i][j][q] = 0.f;

    uint32_t sb = smem_u32(sm);
    uint32_t aBase = sb + (wm * 64 + (lane & 15)) * ARS + (lane >> 4) * 16;

    // gather+convert one relation's A tile: 4 threads/row, 2 passes
    auto gatherA = [&](int rel, int buf) {          // rel<0 -> A = x
        char* bp = sm + buf * A_PLANE;
#pragma unroll
        for (int pass = 0; pass < 2; pass++) {
            int row = pass * 64 + (tid >> 2);
            int quad = tid & 3;                      // 32-float chunk of the row
            int grow = row0 + row;
            char* hiB = bp + row * ARS + quad * 64;
            float4 a4[8];
#pragma unroll
            for (int j = 0; j < 8; j++) a4[j] = make_float4(0.f, 0.f, 0.f, 0.f);
            if (grow < NN) {
                if (rel < 0) {
                    const float4* Ar = (const float4*)x + (size_t)grow * 32 + quad * 8;
#pragma unroll
                    for (int j = 0; j < 8; j++) a4[j] = Ar[j];
                } else {
                    int dg = g_cnt[rel * NN + grow];
                    int rp = g_rowptr[rel * NN + grow] +
                             g_coff[rel * NCHUNK + (grow >> 10)];
                    const int* ep = g_esrc + (size_t)rel * NE + rp;
                    for (int e = 0; e < dg; e++) {
                        int s = ep[e];
                        const float4* Xr = (const float4*)x + (size_t)s * 32 + quad * 8;
#pragma unroll
                        for (int j = 0; j < 8; j++) {
                            float4 v = Xr[j];
                            a4[j].x += v.x; a4[j].y += v.y;
                            a4[j].z += v.z; a4[j].w += v.w;
                        }
                    }
                    float sc = 1.f / (float)(dg > 1 ? dg : 1);
#pragma unroll
                    for (int j = 0; j < 8; j++) {
                        a4[j].x *= sc; a4[j].y *= sc;
                        a4[j].z *= sc; a4[j].w *= sc;
                    }
                }
            }
#pragma unroll
            for (int j = 0; j < 8; j++) {
                *(uint2*)(hiB + j * 8) =
                    make_uint2(pack_h2(a4[j].x, a4[j].y),
                               pack_h2(a4[j].z, a4[j].w));
            }
        }
    };

    gatherA(-1, 0);                                  // rs=0: self-loop, buf 0
    __syncthreads();

    for (int rs = 0; rs < 9; rs++) {
        // ---- MMA on current buffer FIRST (tensor pipe goes busy immediately)
        int wsel = (rs == 0) ? 8 : rs - 1;
        uint32_t ab = aBase + (rs & 1) * A_PLANE;
        const uint4* WF = g_wf + ((size_t)wsel * 64 + wn * 2) * 32 + lane;
#pragma unroll
        for (int kk = 0; kk < 8; kk++) {
            uint32_t a[4][4];
#pragma unroll
            for (int i = 0; i < 4; i++)
                ldsm4(a[i], ab + i * 16 * ARS + kk * 32);
            uint4 f0 = WF[kk * 8 * 32], f1 = WF[kk * 8 * 32 + 32];
#pragma unroll
            for (int i = 0; i < 4; i++) {
                mma16816(acc[i][0], a[i], f0.x, f0.y);
                mma16816(acc[i][1], a[i], f0.z, f0.w);
                mma16816(acc[i][2], a[i], f1.x, f1.y);
                mma16816(acc[i][3], a[i], f1.z, f1.w);
            }
        }
        // ---- then prefetch next relation into the other buffer
        if (rs < 8) gatherA(rs, (rs + 1) & 1);
        __syncthreads();
    }

    // ---- single epilogue: + bias, relu, store
    int g = lane >> 2, tk = lane & 3;
#pragma unroll
    for (int i = 0; i < 4; i++) {
        int r1 = row0 + wm * 64 + i * 16 + g;
#pragma unroll
        for (int jl = 0; jl < 4; jl++) {
            int c = wn * 32 + jl * 8 + tk * 2;
            float b0 = bias[c], b1 = bias[c + 1];
#pragma unroll
            for (int h = 0; h < 2; h++) {
                int row = r1 + h * 8;
                if (row < NN) {
                    float2 v = make_float2(
                        fmaxf(acc[i][jl][h * 2] + b0, 0.f),
                        fmaxf(acc[i][jl][h * 2 + 1] + b1, 0.f));
                    *(float2*)(C + (size_t)row * DD + c) = v;
                }
            }
        }
    }
}

// ---------------------------------------------------------------- launch
extern "C" void kernel_launch(void* const* d_in, const int* in_sizes, int n_in,
                              void* d_out, int out_size) {
    const float* x    = (const float*)d_in[0];
    const float* w    = (const float*)d_in[1];
    const float* wsl  = (const float*)d_in[2];
    const float* bias = (const float*)d_in[3];
    const void* src   = d_in[4];
    const void* dst   = d_in[5];
    float* out = (float*)d_out;

    cudaFuncSetAttribute(fused_gemm_kernel,
                         cudaFuncAttributeMaxDynamicSharedMemorySize, GEMM_SMEM);

    // launch 0: zero deg+fill in one memset
    void* p_cnt = nullptr;
    cudaGetSymbolAddress(&p_cnt, g_cnt);
    cudaMemsetAsync(p_cnt, 0, sizeof(int) * 2 * NR * NN);

    // launches 1-4: CSR build (+W prep fused into scan_a)
    dim3 cg((NE + 255) / 256, NR);
    count_deg_kernel<<<cg, 256>>>(dst);
    dim3 sg(NCHUNK, NR);
    scan_a_kernel<<<sg, 1024>>>(w, wsl);
    scan_b_kernel<<<1, 256>>>();
    fill_kernel<<<cg, 256>>>(src, dst);

    // launch 5: gather + 9 fp16 GEMM passes + epilogue
    fused_gemm_kernel<<<NTILES, 256, GEMM_SMEM>>>(x, bias, out);
}